// round 10
// baseline (speedup 1.0000x reference)
#include <cuda_runtime.h>
#include <cuda_bf16.h>
#include <math.h>
#include <stdint.h>

typedef unsigned u32; typedef unsigned long long ull;
#define NCTA 64
#define ABUF 34816
#define SB1  139264
#define SB1L 155904
#define SB2  172544
#define SB2L 180864
#define SMEM_TOT 189184

__device__ float g_xproj[(size_t)512*128*1536];
__device__ __nv_bfloat16 g_hhi[65536], g_rhhi[65536];
__device__ unsigned g_flags[512];   // one flag per CTA, 32B stride

__device__ __forceinline__ void cp16(void* s, const void* g) {
    u32 a = (u32)__cvta_generic_to_shared(s);
    asm volatile("cp.async.cg.shared.global [%0], [%1], 16;" :: "r"(a), "l"(g));
}
template<int N> __device__ __forceinline__ void cpwait() { asm volatile("cp.async.wait_group %0;" :: "n"(N)); }
__device__ __forceinline__ void cpcommit() { asm volatile("cp.async.commit_group;"); }
__device__ __forceinline__ float hsig(float x) { return fminf(fmaxf(0.2f*x + 0.5f, 0.f), 1.f); }
__device__ __forceinline__ void mma16(float* c, u32 a0, u32 a1, u32 a2, u32 a3, u32 b0, u32 b1) {
    asm volatile("mma.sync.aligned.m16n8k16.row.col.f32.bf16.bf16.f32 "
        "{%0,%1,%2,%3},{%4,%5,%6,%7},{%8,%9},{%0,%1,%2,%3};"
        : "+f"(c[0]), "+f"(c[1]), "+f"(c[2]), "+f"(c[3])
        : "r"(a0), "r"(a1), "r"(a2), "r"(a3), "r"(b0), "r"(b1));
}
__device__ __forceinline__ void wr_hi(__nv_bfloat16* Ah, int off, float v0, float v1) {
    __nv_bfloat16 h0 = __float2bfloat16(v0), h1 = __float2bfloat16(v1);
    *(u32*)(Ah + off) = (u32)__bfloat16_as_ushort(h0) | ((u32)__bfloat16_as_ushort(h1) << 16);
}

__global__ void init_k(const float*) {
    int i = blockIdx.x * 256 + threadIdx.x;
    if (i < 65536) g_hhi[i] = __float2bfloat16(0.f);
    if (i < 512) g_flags[i] = 0u;
}

// ---- verified f32x2 SIMT xproj (round 4) ----
__device__ __forceinline__ ull pk2(float lo, float hi) { ull r; asm("mov.b64 %0,{%1,%2};" : "=l"(r) : "f"(lo), "f"(hi)); return r; }
__device__ __forceinline__ float plo(ull v) { float a, b; asm("mov.b64 {%0,%1},%2;" : "=f"(a), "=f"(b) : "l"(v)); return a; }
__device__ __forceinline__ float phi(ull v) { float a, b; asm("mov.b64 {%0,%1},%2;" : "=f"(a), "=f"(b) : "l"(v)); return b; }
__device__ __forceinline__ void fma2(ull& d, ull a, ull b) { asm("fma.rn.f32x2 %0,%1,%2,%0;" : "+l"(d) : "l"(a), "l"(b)); }

__global__ void __launch_bounds__(256) xproj_k(const float* __restrict__ A, const float* __restrict__ W,
                                               const float* __restrict__ bias) {
    __shared__ float As[16][132], Bs[16][132];
    const int tid = threadIdx.x, m0 = blockIdx.x * 128, n0 = blockIdx.y * 128;
    const int tx = tid & 15, ty = tid >> 4;
    ull acc[8][4];
    #pragma unroll
    for (int i = 0; i < 8; i++) { acc[i][0] = acc[i][1] = acc[i][2] = acc[i][3] = 0ull; }
    for (int kt = 0; kt < 512; kt += 16) {
        int r = tid >> 1, c = (tid & 1) * 8;
        const float* src = A + (size_t)(m0 + r) * 512 + kt + c;
        float4 v0 = *(const float4*)src, v1 = *(const float4*)(src + 4);
        As[c][r] = v0.x; As[c+1][r] = v0.y; As[c+2][r] = v0.z; As[c+3][r] = v0.w;
        As[c+4][r] = v1.x; As[c+5][r] = v1.y; As[c+6][r] = v1.z; As[c+7][r] = v1.w;
        int r2 = tid >> 5, c2 = (tid & 31) * 4;
        #pragma unroll
        for (int j = 0; j < 2; j++)
            *(float4*)&Bs[r2 + j*8][c2] = *(const float4*)(W + (size_t)(kt + r2 + j*8) * 1536 + n0 + c2);
        __syncthreads();
        #pragma unroll
        for (int k = 0; k < 16; k++) {
            float av[8];
            *(float4*)av = *(float4*)&As[k][ty*8]; *(float4*)(av+4) = *(float4*)&As[k][ty*8+4];
            ulonglong2 b01 = *(ulonglong2*)&Bs[k][tx*8], b23 = *(ulonglong2*)&Bs[k][tx*8+4];
            #pragma unroll
            for (int i = 0; i < 8; i++) {
                ull ad = pk2(av[i], av[i]);
                fma2(acc[i][0], ad, b01.x); fma2(acc[i][1], ad, b01.y);
                fma2(acc[i][2], ad, b23.x); fma2(acc[i][3], ad, b23.y);
            }
        }
        __syncthreads();
    }
    #pragma unroll
    for (int i = 0; i < 8; i++) {
        int m = m0 + ty*8 + i, bb = m >> 9, t = m & 511;
        float* dst = g_xproj + (size_t)(t * 128 + bb) * 1536 + n0 + tx*8;
        float o[8];
        #pragma unroll
        for (int j = 0; j < 4; j++) {
            o[2*j]   = plo(acc[i][j]) + bias[n0 + tx*8 + 2*j];
            o[2*j+1] = phi(acc[i][j]) + bias[n0 + tx*8 + 2*j + 1];
        }
        *(float4*)dst = *(float4*)o; *(float4*)(dst+4) = *(float4*)(o+4);
    }
}

// ---- recurrence ----
__device__ __forceinline__ void stageA(char* sm, int kc, const __nv_bfloat16* ghi, int tid) {
    char* dh = sm + kc * ABUF;
    #pragma unroll
    for (int j = 0; j < 8; j++) {
        int v = tid + j * 256, b = v >> 4, u = v & 15;
        cp16(dh + b * 272 + u * 16, ghi + b * 512 + kc * 128 + u * 8);
    }
    cpcommit();
}

__device__ __forceinline__ void gbar(int tid, unsigned seq) {
    __threadfence();
    __syncthreads();
    if (tid == 0)
        asm volatile("st.release.gpu.global.u32 [%0], %1;" :: "l"(g_flags + blockIdx.x * 8), "r"(seq));
    if (tid < 64) {
        unsigned v;
        do { asm volatile("ld.acquire.gpu.global.u32 %0, [%1];" : "=r"(v) : "l"(g_flags + tid * 8)); } while (v < seq);
    }
    __syncthreads();
}

template<int NBLK>
__device__ __forceinline__ void mma_phase(char* sm, const __nv_bfloat16* ghi,
                                          int sb, int sbl, float (*acc)[4], int tid, int arow, int gr, int tig) {
    stageA(sm, 0, ghi, tid); stageA(sm, 1, ghi, tid);
    stageA(sm, 2, ghi, tid); stageA(sm, 3, ghi, tid);
    #pragma unroll
    for (int c = 0; c < 4; c++) {
        if (c == 0) cpwait<3>(); else if (c == 1) cpwait<2>(); else if (c == 2) cpwait<1>(); else cpwait<0>();
        __syncthreads();
        const char* ah = sm + c * ABUF + arow * 272 + tig * 4;
        #pragma unroll
        for (int ks = 0; ks < 8; ks++) {
            int ko = ks * 32;
            u32 a0 = *(const u32*)(ah + ko),      a1 = *(const u32*)(ah + ko + 8*272);
            u32 a2 = *(const u32*)(ah + ko + 16), a3 = *(const u32*)(ah + ko + 16 + 8*272);
            #pragma unroll
            for (int nb = 0; nb < NBLK; nb++) {
                int bo = (nb * 8 + gr) * 1040 + c * 256 + ks * 32 + tig * 4;
                u32 b0 = *(const u32*)(sm + sb + bo),  b1 = *(const u32*)(sm + sb + bo + 16);
                u32 c0 = *(const u32*)(sm + sbl + bo), c1 = *(const u32*)(sm + sbl + bo + 16);
                mma16(acc[nb], a0, a1, a2, a3, b0, b1);
                mma16(acc[nb], a0, a1, a2, a3, c0, c1);
            }
        }
    }
}

__global__ void __launch_bounds__(256, 1) rec_k(const float* __restrict__ RK,
                                                const float* __restrict__ attn,
                                                float* __restrict__ out) {
    extern __shared__ char sm[];
    const int tid = threadIdx.x, w = tid >> 5, lane = tid & 31, gr = lane >> 2, tig = lane & 3;
    const int u0 = blockIdx.x * 8;
    for (int idx = tid; idx < 16 * 512; idx += 256) {
        int n = idx >> 9, k = idx & 511;
        int col = n < 8 ? (u0 + n) : (512 + u0 + n - 8);
        float v = RK[(size_t)k * 1536 + col];
        __nv_bfloat16 h = __float2bfloat16(v), l = __float2bfloat16(v - __bfloat162float(h));
        *(__nv_bfloat16*)(sm + SB1 + n*1040 + k*2) = h;
        *(__nv_bfloat16*)(sm + SB1L + n*1040 + k*2) = l;
    }
    for (int idx = tid; idx < 8 * 512; idx += 256) {
        int n = idx >> 9, k = idx & 511;
        float v = RK[(size_t)k * 1536 + 1024 + u0 + n];
        __nv_bfloat16 h = __float2bfloat16(v), l = __float2bfloat16(v - __bfloat162float(h));
        *(__nv_bfloat16*)(sm + SB2 + n*1040 + k*2) = h;
        *(__nv_bfloat16*)(sm + SB2L + n*1040 + k*2) = l;
    }
    __syncthreads();

    const int b0r = w * 16 + gr, b1r = b0r + 8, arow = b0r;
    const int uc = u0 + tig * 2;
    float h00 = 0.f, h01 = 0.f, h10 = 0.f, h11 = 0.f;
    float z00, z01, z10, z11;

    for (int t = 0; t < 512; t++) {
        // prefetch x_proj slices + attn for this step (hidden under staging/mma)
        const float* x0 = g_xproj + ((size_t)t * 128 + b0r) * 1536 + uc;
        const float* x1 = g_xproj + ((size_t)t * 128 + b1r) * 1536 + uc;
        float2 xz0 = *(const float2*)x0, xr0 = *(const float2*)(x0 + 512), xh0 = *(const float2*)(x0 + 1024);
        float2 xz1 = *(const float2*)x1, xr1 = *(const float2*)(x1 + 512), xh1 = *(const float2*)(x1 + 1024);
        float av0 = attn[b0r * 512 + t], av1 = attn[b1r * 512 + t];

        float a1[2][4] = {{0,0,0,0},{0,0,0,0}};
        mma_phase<2>(sm, g_hhi, SB1, SB1L, a1, tid, arow, gr, tig);
        z00 = hsig(xz0.x + a1[0][0]); z01 = hsig(xz0.y + a1[0][1]);
        z10 = hsig(xz1.x + a1[0][2]); z11 = hsig(xz1.y + a1[0][3]);
        {
            float r00 = hsig(xr0.x + a1[1][0]), r01 = hsig(xr0.y + a1[1][1]);
            float r10 = hsig(xr1.x + a1[1][2]), r11 = hsig(xr1.y + a1[1][3]);
            wr_hi(g_rhhi, b0r * 512 + uc, r00 * h00, r01 * h01);
            wr_hi(g_rhhi, b1r * 512 + uc, r10 * h10, r11 * h11);
        }
        gbar(tid, 2 * t + 1);

        float a2[1][4] = {{0,0,0,0}};
        mma_phase<1>(sm, g_rhhi, SB2, SB2L, a2, tid, arow, gr, tig);
        {
            float hh;
            hh = tanhf(xh0.x + a2[0][0]); hh = z00 * h00 + (1.f - z00) * hh; h00 = av0 * hh + (1.f - av0) * h00;
            hh = tanhf(xh0.y + a2[0][1]); hh = z01 * h01 + (1.f - z01) * hh; h01 = av0 * hh + (1.f - av0) * h01;
            hh = tanhf(xh1.x + a2[0][2]); hh = z10 * h10 + (1.f - z10) * hh; h10 = av1 * hh + (1.f - av1) * h10;
            hh = tanhf(xh1.y + a2[0][3]); hh = z11 * h11 + (1.f - z11) * hh; h11 = av1 * hh + (1.f - av1) * h11;
            wr_hi(g_hhi, b0r * 512 + uc, h00, h01);
            wr_hi(g_hhi, b1r * 512 + uc, h10, h11);
            if (t == 511) {
                *(float2*)(out + b0r * 512 + uc) = make_float2(h00, h01);
                *(float2*)(out + b1r * 512 + uc) = make_float2(h10, h11);
            }
        }
        gbar(tid, 2 * t + 2);
    }
}

extern "C" void kernel_launch(void* const* d_in, const int* in_sizes, int n_in,
                              void* d_out, int out_size) {
    cudaFuncSetAttribute(rec_k, cudaFuncAttributeMaxDynamicSharedMemorySize, SMEM_TOT);
    init_k<<<256, 256>>>((const float*)d_in[1]);
    xproj_k<<<dim3(512, 12), 256>>>((const float*)d_in[0], (const float*)d_in[2], (const float*)d_in[4]);
    rec_k<<<NCTA, 256, SMEM_TOT>>>((const float*)d_in[3], (const float*)d_in[1], (float*)d_out);
}

// round 14
// speedup vs baseline: 1.2671x; 1.2671x over previous
#include <cuda_runtime.h>
#include <cuda_bf16.h>
#include <math.h>
#include <stdint.h>

typedef unsigned u32; typedef unsigned long long ull;
#define NCTA 64
// rec smem (round-9 verified)
#define ABUF 34816
#define SB1  69632
#define SB1L 86272
#define SB2  102912
#define SB2L 111232
#define REC_SMEM 119552
// xproj smem: 4 planes of 128 rows x 80B per buffer, 2 buffers
#define XPLN 10240
#define XBUF 40960
#define XP_SMEM 81920

__device__ float g_xproj[(size_t)512*128*1536];
__device__ __nv_bfloat16 g_hhi[65536], g_rhhi[65536];
__device__ __nv_bfloat16 g_inhi[(size_t)128*512*512], g_inlo[(size_t)128*512*512];
__device__ __nv_bfloat16 g_wthi[1536*512], g_wtlo[1536*512];
__device__ unsigned g_bar;

__device__ __forceinline__ void cp16(void* s, const void* g) {
    u32 a = (u32)__cvta_generic_to_shared(s);
    asm volatile("cp.async.cg.shared.global [%0], [%1], 16;" :: "r"(a), "l"(g));
}
template<int N> __device__ __forceinline__ void cpwait() { asm volatile("cp.async.wait_group %0;" :: "n"(N)); }
__device__ __forceinline__ void cpcommit() { asm volatile("cp.async.commit_group;"); }
__device__ __forceinline__ unsigned ldbar() {
    unsigned v; asm volatile("ld.acquire.gpu.global.u32 %0, [%1];" : "=r"(v) : "l"(&g_bar)); return v;
}
__device__ __forceinline__ float hsig(float x) { return fminf(fmaxf(0.2f*x + 0.5f, 0.f), 1.f); }
__device__ __forceinline__ void mma16(float* c, u32 a0, u32 a1, u32 a2, u32 a3, u32 b0, u32 b1) {
    asm volatile("mma.sync.aligned.m16n8k16.row.col.f32.bf16.bf16.f32 "
        "{%0,%1,%2,%3},{%4,%5,%6,%7},{%8,%9},{%0,%1,%2,%3};"
        : "+f"(c[0]), "+f"(c[1]), "+f"(c[2]), "+f"(c[3])
        : "r"(a0), "r"(a1), "r"(a2), "r"(a3), "r"(b0), "r"(b1));
}
__device__ __forceinline__ void wr_hi(__nv_bfloat16* Ah, int off, float v0, float v1) {
    __nv_bfloat16 h0 = __float2bfloat16(v0), h1 = __float2bfloat16(v1);
    *(u32*)(Ah + off) = (u32)__bfloat16_as_ushort(h0) | ((u32)__bfloat16_as_ushort(h1) << 16);
}
__device__ __forceinline__ u32 pkb(float v0, float v1, u32& lo) {
    __nv_bfloat16 h0 = __float2bfloat16(v0), h1 = __float2bfloat16(v1);
    __nv_bfloat16 l0 = __float2bfloat16(v0 - __bfloat162float(h0));
    __nv_bfloat16 l1 = __float2bfloat16(v1 - __bfloat162float(h1));
    lo = (u32)__bfloat16_as_ushort(l0) | ((u32)__bfloat16_as_ushort(l1) << 16);
    return (u32)__bfloat16_as_ushort(h0) | ((u32)__bfloat16_as_ushort(h1) << 16);
}

__global__ void init_k(const float*) {
    int i = blockIdx.x * 256 + threadIdx.x;
    if (i < 65536) g_hhi[i] = __float2bfloat16(0.f);
    if (i == 0) g_bar = 0u;
}

__global__ void prep_in_k(const float* __restrict__ A) {
    size_t i = ((size_t)blockIdx.x * 256 + threadIdx.x) * 8;
    float4 v0 = *(const float4*)(A + i), v1 = *(const float4*)(A + i + 4);
    uint4 h, l;
    h.x = pkb(v0.x, v0.y, l.x); h.y = pkb(v0.z, v0.w, l.y);
    h.z = pkb(v1.x, v1.y, l.z); h.w = pkb(v1.z, v1.w, l.w);
    *(uint4*)(g_inhi + i) = h; *(uint4*)(g_inlo + i) = l;
}
__global__ void prep_w_k(const float* __restrict__ W) {
    int n = blockIdx.y * 256 + threadIdx.x, k = blockIdx.x;
    float v = W[(size_t)k * 1536 + n];
    __nv_bfloat16 h = __float2bfloat16(v), l = __float2bfloat16(v - __bfloat162float(h));
    g_wthi[(size_t)n * 512 + k] = h; g_wtlo[(size_t)n * 512 + k] = l;
}

// ---- tensor-core xproj: C[m][n] = in @ Wt^T + bias, bf16x3 ----
__global__ void __launch_bounds__(256) xproj_t_k(const float* __restrict__ bias) {
    extern __shared__ char sx[];
    const int tid = threadIdx.x, w = tid >> 5, lane = tid & 31;
    const int gr = lane >> 2, tig = lane & 3, wm = w & 1, wn = w >> 1;
    const int m0 = blockIdx.x * 128, n0 = blockIdx.y * 128;
    float acc[4][4][4];
    #pragma unroll
    for (int i = 0; i < 4; i++)
        #pragma unroll
        for (int j = 0; j < 4; j++)
            #pragma unroll
            for (int e = 0; e < 4; e++) acc[i][j][e] = 0.f;

    auto stage = [&](int c) {
        char* base = sx + (c & 1) * XBUF;
        #pragma unroll
        for (int j = 0; j < 8; j++) {
            int idx = tid + j * 256;
            int mat = idx >> 9, r = (idx >> 2) & 127, q = idx & 3;
            const __nv_bfloat16* src;
            if (mat == 0)      src = g_inhi + (size_t)(m0 + r) * 512 + c * 32 + q * 8;
            else if (mat == 1) src = g_inlo + (size_t)(m0 + r) * 512 + c * 32 + q * 8;
            else if (mat == 2) src = g_wthi + (size_t)(n0 + r) * 512 + c * 32 + q * 8;
            else               src = g_wtlo + (size_t)(n0 + r) * 512 + c * 32 + q * 8;
            cp16(base + mat * XPLN + r * 80 + q * 16, src);
        }
        cpcommit();
    };

    stage(0);
    for (int c = 0; c < 16; c++) {
        if (c < 15) { stage(c + 1); cpwait<1>(); } else cpwait<0>();
        __syncthreads();
        const char* base = sx + (c & 1) * XBUF;
        #pragma unroll
        for (int k16 = 0; k16 < 2; k16++) {
            int kb = k16 * 32 + tig * 4;
            u32 ah[4][4], al[4][4];
            #pragma unroll
            for (int mf = 0; mf < 4; mf++) {
                int row = wm * 64 + mf * 16 + gr;
                const char* pa = base + row * 80 + kb;
                ah[mf][0] = *(const u32*)(pa);            ah[mf][1] = *(const u32*)(pa + 8*80);
                ah[mf][2] = *(const u32*)(pa + 16);       ah[mf][3] = *(const u32*)(pa + 8*80 + 16);
                const char* pl = pa + XPLN;
                al[mf][0] = *(const u32*)(pl);            al[mf][1] = *(const u32*)(pl + 8*80);
                al[mf][2] = *(const u32*)(pl + 16);       al[mf][3] = *(const u32*)(pl + 8*80 + 16);
            }
            #pragma unroll
            for (int nf = 0; nf < 4; nf++) {
                int row = wn * 32 + nf * 8 + gr;
                const char* pb = base + 2 * XPLN + row * 80 + kb;
                u32 b0 = *(const u32*)(pb), b1 = *(const u32*)(pb + 16);
                u32 c0 = *(const u32*)(pb + XPLN), c1 = *(const u32*)(pb + XPLN + 16);
                #pragma unroll
                for (int mf = 0; mf < 4; mf++) {
                    mma16(acc[mf][nf], ah[mf][0], ah[mf][1], ah[mf][2], ah[mf][3], b0, b1);
                    mma16(acc[mf][nf], al[mf][0], al[mf][1], al[mf][2], al[mf][3], b0, b1);
                    mma16(acc[mf][nf], ah[mf][0], ah[mf][1], ah[mf][2], ah[mf][3], c0, c1);
                }
            }
        }
        __syncthreads();
    }

    #pragma unroll
    for (int nf = 0; nf < 4; nf++) {
        int n = n0 + wn * 32 + nf * 8 + tig * 2;
        float2 bb = *(const float2*)(bias + n);
        #pragma unroll
        for (int mf = 0; mf < 4; mf++) {
            int r0 = m0 + wm * 64 + mf * 16 + gr;
            int r1 = r0 + 8;
            float* d0 = g_xproj + (size_t)((r0 & 511) * 128 + (r0 >> 9)) * 1536 + n;
            float* d1 = g_xproj + (size_t)((r1 & 511) * 128 + (r1 >> 9)) * 1536 + n;
            *(float2*)d0 = make_float2(acc[mf][nf][0] + bb.x, acc[mf][nf][1] + bb.y);
            *(float2*)d1 = make_float2(acc[mf][nf][2] + bb.x, acc[mf][nf][3] + bb.y);
        }
    }
}

// ---- recurrence: round-9 verified (8096us), unchanged ----
__device__ __forceinline__ void stageA(char* sm, int kc, const __nv_bfloat16* ghi, int tid) {
    char* dh = sm + (kc & 1) * ABUF;
    #pragma unroll
    for (int j = 0; j < 8; j++) {
        int v = tid + j * 256, b = v >> 4, u = v & 15;
        cp16(dh + b * 272 + u * 16, ghi + b * 512 + kc * 128 + u * 8);
    }
    cpcommit();
}
__device__ __forceinline__ void gbar(int tid, unsigned tgt) {
    __threadfence(); __syncthreads();
    if (tid == 0) { atomicAdd(&g_bar, 1u); while (ldbar() < tgt * NCTA) {} }
    __syncthreads();
}
template<int NBLK>
__device__ __forceinline__ void mma_phase(char* sm, const __nv_bfloat16* ghi,
                                          int sb, int sbl, float (*acc)[4], int tid, int arow, int gr, int tig) {
    stageA(sm, 0, ghi, tid);
    for (int c = 0; c < 4; c++) {
        if (c < 3) { stageA(sm, c + 1, ghi, tid); cpwait<1>(); } else cpwait<0>();
        __syncthreads();
        const char* ah = sm + (c & 1) * ABUF + arow * 272 + tig * 4;
        #pragma unroll
        for (int ks = 0; ks < 8; ks++) {
            int ko = ks * 32;
            u32 a0 = *(const u32*)(ah + ko),      a1 = *(const u32*)(ah + ko + 8*272);
            u32 a2 = *(const u32*)(ah + ko + 16), a3 = *(const u32*)(ah + ko + 16 + 8*272);
            #pragma unroll
            for (int nb = 0; nb < NBLK; nb++) {
                int bo = (nb * 8 + gr) * 1040 + c * 256 + ks * 32 + tig * 4;
                u32 b0 = *(const u32*)(sm + sb + bo),  b1 = *(const u32*)(sm + sb + bo + 16);
                u32 c0 = *(const u32*)(sm + sbl + bo), c1 = *(const u32*)(sm + sbl + bo + 16);
                mma16(acc[nb], a0, a1, a2, a3, b0, b1);
                mma16(acc[nb], a0, a1, a2, a3, c0, c1);
            }
        }
        __syncthreads();
    }
}

__global__ void __launch_bounds__(256, 1) rec_k(const float* __restrict__ RK,
                                                const float* __restrict__ attn,
                                                float* __restrict__ out) {
    extern __shared__ char sm[];
    const int tid = threadIdx.x, w = tid >> 5, lane = tid & 31, gr = lane >> 2, tig = lane & 3;
    const int u0 = blockIdx.x * 8;
    for (int idx = tid; idx < 16 * 512; idx += 256) {
        int n = idx >> 9, k = idx & 511;
        int col = n < 8 ? (u0 + n) : (512 + u0 + n - 8);
        float v = RK[(size_t)k * 1536 + col];
        __nv_bfloat16 h = __float2bfloat16(v), l = __float2bfloat16(v - __bfloat162float(h));
        *(__nv_bfloat16*)(sm + SB1 + n*1040 + k*2) = h;
        *(__nv_bfloat16*)(sm + SB1L + n*1040 + k*2) = l;
    }
    for (int idx = tid; idx < 8 * 512; idx += 256) {
        int n = idx >> 9, k = idx & 511;
        float v = RK[(size_t)k * 1536 + 1024 + u0 + n];
        __nv_bfloat16 h = __float2bfloat16(v), l = __float2bfloat16(v - __bfloat162float(h));
        *(__nv_bfloat16*)(sm + SB2 + n*1040 + k*2) = h;
        *(__nv_bfloat16*)(sm + SB2L + n*1040 + k*2) = l;
    }
    __syncthreads();

    const int b0r = w * 16 + gr, b1r = b0r + 8, arow = b0r;
    const int uc = u0 + tig * 2;
    float h00 = 0.f, h01 = 0.f, h10 = 0.f, h11 = 0.f;
    float z00, z01, z10, z11;

    for (int t = 0; t < 512; t++) {
        float a1[2][4] = {{0,0,0,0},{0,0,0,0}};
        mma_phase<2>(sm, g_hhi, SB1, SB1L, a1, tid, arow, gr, tig);
        {
            const float* x0 = g_xproj + ((size_t)t * 128 + b0r) * 1536 + uc;
            const float* x1 = g_xproj + ((size_t)t * 128 + b1r) * 1536 + uc;
            float2 xz0 = *(const float2*)x0, xr0 = *(const float2*)(x0 + 512);
            float2 xz1 = *(const float2*)x1, xr1 = *(const float2*)(x1 + 512);
            z00 = hsig(xz0.x + a1[0][0]); z01 = hsig(xz0.y + a1[0][1]);
            z10 = hsig(xz1.x + a1[0][2]); z11 = hsig(xz1.y + a1[0][3]);
            float r00 = hsig(xr0.x + a1[1][0]), r01 = hsig(xr0.y + a1[1][1]);
            float r10 = hsig(xr1.x + a1[1][2]), r11 = hsig(xr1.y + a1[1][3]);
            wr_hi(g_rhhi, b0r * 512 + uc, r00 * h00, r01 * h01);
            wr_hi(g_rhhi, b1r * 512 + uc, r10 * h10, r11 * h11);
        }
        gbar(tid, 2 * t + 1);

        float a2[1][4] = {{0,0,0,0}};
        mma_phase<1>(sm, g_rhhi, SB2, SB2L, a2, tid, arow, gr, tig);
        {
            const float* x0 = g_xproj + ((size_t)t * 128 + b0r) * 1536 + 1024 + uc;
            const float* x1 = g_xproj + ((size_t)t * 128 + b1r) * 1536 + 1024 + uc;
            float2 xh0 = *(const float2*)x0, xh1 = *(const float2*)x1;
            float av0 = attn[b0r * 512 + t], av1 = attn[b1r * 512 + t];
            float hh;
            hh = tanhf(xh0.x + a2[0][0]); hh = z00 * h00 + (1.f - z00) * hh; h00 = av0 * hh + (1.f - av0) * h00;
            hh = tanhf(xh0.y + a2[0][1]); hh = z01 * h01 + (1.f - z01) * hh; h01 = av0 * hh + (1.f - av0) * h01;
            hh = tanhf(xh1.x + a2[0][2]); hh = z10 * h10 + (1.f - z10) * hh; h10 = av1 * hh + (1.f - av1) * h10;
            hh = tanhf(xh1.y + a2[0][3]); hh = z11 * h11 + (1.f - z11) * hh; h11 = av1 * hh + (1.f - av1) * h11;
            wr_hi(g_hhi, b0r * 512 + uc, h00, h01);
            wr_hi(g_hhi, b1r * 512 + uc, h10, h11);
            if (t == 511) {
                *(float2*)(out + b0r * 512 + uc) = make_float2(h00, h01);
                *(float2*)(out + b1r * 512 + uc) = make_float2(h10, h11);
            }
        }
        gbar(tid, 2 * t + 2);
    }
}

extern "C" void kernel_launch(void* const* d_in, const int* in_sizes, int n_in,
                              void* d_out, int out_size) {
    cudaFuncSetAttribute(rec_k, cudaFuncAttributeMaxDynamicSharedMemorySize, REC_SMEM);
    cudaFuncSetAttribute(xproj_t_k, cudaFuncAttributeMaxDynamicSharedMemorySize, XP_SMEM);
    init_k<<<256, 256>>>((const float*)d_in[1]);
    prep_in_k<<<16384, 256>>>((const float*)d_in[0]);
    prep_w_k<<<dim3(512, 6), 256>>>((const float*)d_in[2]);
    xproj_t_k<<<dim3(512, 12), 256, XP_SMEM>>>((const float*)d_in[4]);
    rec_k<<<NCTA, 256, REC_SMEM>>>((const float*)d_in[3], (const float*)d_in[1], (float*)d_out);
}

// round 16
// speedup vs baseline: 1.3207x; 1.0423x over previous
#include <cuda_runtime.h>
#include <cuda_bf16.h>
#include <math.h>
#include <stdint.h>

typedef unsigned u32; typedef unsigned long long ull;
#define NCTA 64
#define ABUF 34816
#define SB1  69632
#define SB1L 86272
#define SB2  102912
#define SB2L 111232
#define REC_SMEM 119552
#define XPLN 10240
#define XBUF 40960
#define XP_SMEM 81920

__device__ float g_xproj[(size_t)512*128*1536];
__device__ __nv_bfloat16 g_hhi[65536], g_rhhi[65536];
__device__ __nv_bfloat16 g_inhi[(size_t)128*512*512], g_inlo[(size_t)128*512*512];
__device__ __nv_bfloat16 g_wthi[1536*512], g_wtlo[1536*512];
__device__ unsigned g_bar;

__device__ __forceinline__ void cp16(void* s, const void* g) {
    u32 a = (u32)__cvta_generic_to_shared(s);
    asm volatile("cp.async.cg.shared.global [%0], [%1], 16;" :: "r"(a), "l"(g));
}
template<int N> __device__ __forceinline__ void cpwait() { asm volatile("cp.async.wait_group %0;" :: "n"(N)); }
__device__ __forceinline__ void cpcommit() { asm volatile("cp.async.commit_group;"); }
__device__ __forceinline__ float hsig(float x) { return fminf(fmaxf(0.2f*x + 0.5f, 0.f), 1.f); }
__device__ __forceinline__ void mma16(float* c, u32 a0, u32 a1, u32 a2, u32 a3, u32 b0, u32 b1) {
    asm volatile("mma.sync.aligned.m16n8k16.row.col.f32.bf16.bf16.f32 "
        "{%0,%1,%2,%3},{%4,%5,%6,%7},{%8,%9},{%0,%1,%2,%3};"
        : "+f"(c[0]), "+f"(c[1]), "+f"(c[2]), "+f"(c[3])
        : "r"(a0), "r"(a1), "r"(a2), "r"(a3), "r"(b0), "r"(b1));
}
__device__ __forceinline__ void wr_hi(__nv_bfloat16* Ah, int off, float v0, float v1) {
    __nv_bfloat16 h0 = __float2bfloat16(v0), h1 = __float2bfloat16(v1);
    *(u32*)(Ah + off) = (u32)__bfloat16_as_ushort(h0) | ((u32)__bfloat16_as_ushort(h1) << 16);
}
__device__ __forceinline__ u32 pkb(float v0, float v1, u32& lo) {
    __nv_bfloat16 h0 = __float2bfloat16(v0), h1 = __float2bfloat16(v1);
    __nv_bfloat16 l0 = __float2bfloat16(v0 - __bfloat162float(h0));
    __nv_bfloat16 l1 = __float2bfloat16(v1 - __bfloat162float(h1));
    lo = (u32)__bfloat16_as_ushort(l0) | ((u32)__bfloat16_as_ushort(l1) << 16);
    return (u32)__bfloat16_as_ushort(h0) | ((u32)__bfloat16_as_ushort(h1) << 16);
}

// no-op: shifts rec_k to launch #6 so ncu (-s 5 -c 1) profiles it
__global__ void noop_k() {}

__global__ void init_k(const float*) {
    int i = blockIdx.x * 256 + threadIdx.x;
    if (i < 65536) g_hhi[i] = __float2bfloat16(0.f);
    if (i == 0) g_bar = 0u;
}

__global__ void prep_in_k(const float* __restrict__ A) {
    size_t i = ((size_t)blockIdx.x * 256 + threadIdx.x) * 8;
    float4 v0 = *(const float4*)(A + i), v1 = *(const float4*)(A + i + 4);
    uint4 h, l;
    h.x = pkb(v0.x, v0.y, l.x); h.y = pkb(v0.z, v0.w, l.y);
    h.z = pkb(v1.x, v1.y, l.z); h.w = pkb(v1.z, v1.w, l.w);
    *(uint4*)(g_inhi + i) = h; *(uint4*)(g_inlo + i) = l;
}
__global__ void prep_w_k(const float* __restrict__ W) {
    int n = blockIdx.y * 256 + threadIdx.x, k = blockIdx.x;
    float v = W[(size_t)k * 1536 + n];
    __nv_bfloat16 h = __float2bfloat16(v), l = __float2bfloat16(v - __bfloat162float(h));
    g_wthi[(size_t)n * 512 + k] = h; g_wtlo[(size_t)n * 512 + k] = l;
}

// ---- tensor-core xproj (round-14 verified) ----
__global__ void __launch_bounds__(256) xproj_t_k(const float* __restrict__ bias) {
    extern __shared__ char sx[];
    const int tid = threadIdx.x, w = tid >> 5, lane = tid & 31;
    const int gr = lane >> 2, tig = lane & 3, wm = w & 1, wn = w >> 1;
    const int m0 = blockIdx.x * 128, n0 = blockIdx.y * 128;
    float acc[4][4][4];
    #pragma unroll
    for (int i = 0; i < 4; i++)
        #pragma unroll
        for (int j = 0; j < 4; j++)
            #pragma unroll
            for (int e = 0; e < 4; e++) acc[i][j][e] = 0.f;

    auto stage = [&](int c) {
        char* base = sx + (c & 1) * XBUF;
        #pragma unroll
        for (int j = 0; j < 8; j++) {
            int idx = tid + j * 256;
            int mat = idx >> 9, r = (idx >> 2) & 127, q = idx & 3;
            const __nv_bfloat16* src;
            if (mat == 0)      src = g_inhi + (size_t)(m0 + r) * 512 + c * 32 + q * 8;
            else if (mat == 1) src = g_inlo + (size_t)(m0 + r) * 512 + c * 32 + q * 8;
            else if (mat == 2) src = g_wthi + (size_t)(n0 + r) * 512 + c * 32 + q * 8;
            else               src = g_wtlo + (size_t)(n0 + r) * 512 + c * 32 + q * 8;
            cp16(base + mat * XPLN + r * 80 + q * 16, src);
        }
        cpcommit();
    };

    stage(0);
    for (int c = 0; c < 16; c++) {
        if (c < 15) { stage(c + 1); cpwait<1>(); } else cpwait<0>();
        __syncthreads();
        const char* base = sx + (c & 1) * XBUF;
        #pragma unroll
        for (int k16 = 0; k16 < 2; k16++) {
            int kb = k16 * 32 + tig * 4;
            u32 ah[4][4], al[4][4];
            #pragma unroll
            for (int mf = 0; mf < 4; mf++) {
                int row = wm * 64 + mf * 16 + gr;
                const char* pa = base + row * 80 + kb;
                ah[mf][0] = *(const u32*)(pa);            ah[mf][1] = *(const u32*)(pa + 8*80);
                ah[mf][2] = *(const u32*)(pa + 16);       ah[mf][3] = *(const u32*)(pa + 8*80 + 16);
                const char* pl = pa + XPLN;
                al[mf][0] = *(const u32*)(pl);            al[mf][1] = *(const u32*)(pl + 8*80);
                al[mf][2] = *(const u32*)(pl + 16);       al[mf][3] = *(const u32*)(pl + 8*80 + 16);
            }
            #pragma unroll
            for (int nf = 0; nf < 4; nf++) {
                int row = wn * 32 + nf * 8 + gr;
                const char* pb = base + 2 * XPLN + row * 80 + kb;
                u32 b0 = *(const u32*)(pb), b1 = *(const u32*)(pb + 16);
                u32 c0 = *(const u32*)(pb + XPLN), c1 = *(const u32*)(pb + XPLN + 16);
                #pragma unroll
                for (int mf = 0; mf < 4; mf++) {
                    mma16(acc[mf][nf], ah[mf][0], ah[mf][1], ah[mf][2], ah[mf][3], b0, b1);
                    mma16(acc[mf][nf], al[mf][0], al[mf][1], al[mf][2], al[mf][3], b0, b1);
                    mma16(acc[mf][nf], ah[mf][0], ah[mf][1], ah[mf][2], ah[mf][3], c0, c1);
                }
            }
        }
        __syncthreads();
    }

    #pragma unroll
    for (int nf = 0; nf < 4; nf++) {
        int n = n0 + wn * 32 + nf * 8 + tig * 2;
        float2 bb = *(const float2*)(bias + n);
        #pragma unroll
        for (int mf = 0; mf < 4; mf++) {
            int r0 = m0 + wm * 64 + mf * 16 + gr;
            int r1 = r0 + 8;
            float* d0 = g_xproj + (size_t)((r0 & 511) * 128 + (r0 >> 9)) * 1536 + n;
            float* d1 = g_xproj + (size_t)((r1 & 511) * 128 + (r1 >> 9)) * 1536 + n;
            *(float2*)d0 = make_float2(acc[mf][nf][0] + bb.x, acc[mf][nf][1] + bb.y);
            *(float2*)d1 = make_float2(acc[mf][nf][2] + bb.x, acc[mf][nf][3] + bb.y);
        }
    }
}

// ---- recurrence: round-9 structure; ONLY the barrier changed this round ----
__device__ __forceinline__ void stageA(char* sm, int kc, const __nv_bfloat16* ghi, int tid) {
    char* dh = sm + (kc & 1) * ABUF;
    #pragma unroll
    for (int j = 0; j < 8; j++) {
        int v = tid + j * 256, b = v >> 4, u = v & 15;
        cp16(dh + b * 272 + u * 16, ghi + b * 512 + kc * 128 + u * 8);
    }
    cpcommit();
}
// new barrier: release-red arrival (no fence, no ATOMG return wait) + acquire poll
__device__ __forceinline__ void gbar(int tid, unsigned tgt) {
    __syncthreads();                       // all epilogue STGs happen-before tid0's release
    if (tid == 0) {
        asm volatile("red.release.gpu.global.add.u32 [%0], %1;" :: "l"(&g_bar), "r"(1u) : "memory");
        unsigned v;
        do { asm volatile("ld.acquire.gpu.global.u32 %0, [%1];" : "=r"(v) : "l"(&g_bar)); } while (v < tgt * NCTA);
    }
    __syncthreads();
}
template<int NBLK>
__device__ __forceinline__ void mma_phase(char* sm, const __nv_bfloat16* ghi,
                                          int sb, int sbl, float (*acc)[4], int tid, int arow, int gr, int tig) {
    stageA(sm, 0, ghi, tid);
    for (int c = 0; c < 4; c++) {
        if (c < 3) { stageA(sm, c + 1, ghi, tid); cpwait<1>(); } else cpwait<0>();
        __syncthreads();
        const char* ah = sm + (c & 1) * ABUF + arow * 272 + tig * 4;
        #pragma unroll
        for (int ks = 0; ks < 8; ks++) {
            int ko = ks * 32;
            u32 a0 = *(const u32*)(ah + ko),      a1 = *(const u32*)(ah + ko + 8*272);
            u32 a2 = *(const u32*)(ah + ko + 16), a3 = *(const u32*)(ah + ko + 16 + 8*272);
            #pragma unroll
            for (int nb = 0; nb < NBLK; nb++) {
                int bo = (nb * 8 + gr) * 1040 + c * 256 + ks * 32 + tig * 4;
                u32 b0 = *(const u32*)(sm + sb + bo),  b1 = *(const u32*)(sm + sb + bo + 16);
                u32 c0 = *(const u32*)(sm + sbl + bo), c1 = *(const u32*)(sm + sbl + bo + 16);
                mma16(acc[nb], a0, a1, a2, a3, b0, b1);
                mma16(acc[nb], a0, a1, a2, a3, c0, c1);
            }
        }
        __syncthreads();
    }
}

__global__ void __launch_bounds__(256, 1) rec_k(const float* __restrict__ RK,
                                                const float* __restrict__ attn,
                                                float* __restrict__ out) {
    extern __shared__ char sm[];
    const int tid = threadIdx.x, w = tid >> 5, lane = tid & 31, gr = lane >> 2, tig = lane & 3;
    const int u0 = blockIdx.x * 8;
    for (int idx = tid; idx < 16 * 512; idx += 256) {
        int n = idx >> 9, k = idx & 511;
        int col = n < 8 ? (u0 + n) : (512 + u0 + n - 8);
        float v = RK[(size_t)k * 1536 + col];
        __nv_bfloat16 h = __float2bfloat16(v), l = __float2bfloat16(v - __bfloat162float(h));
        *(__nv_bfloat16*)(sm + SB1 + n*1040 + k*2) = h;
        *(__nv_bfloat16*)(sm + SB1L + n*1040 + k*2) = l;
    }
    for (int idx = tid; idx < 8 * 512; idx += 256) {
        int n = idx >> 9, k = idx & 511;
        float v = RK[(size_t)k * 1536 + 1024 + u0 + n];
        __nv_bfloat16 h = __float2bfloat16(v), l = __float2bfloat16(v - __bfloat162float(h));
        *(__nv_bfloat16*)(sm + SB2 + n*1040 + k*2) = h;
        *(__nv_bfloat16*)(sm + SB2L + n*1040 + k*2) = l;
    }
    __syncthreads();

    const int b0r = w * 16 + gr, b1r = b0r + 8, arow = b0r;
    const int uc = u0 + tig * 2;
    float h00 = 0.f, h01 = 0.f, h10 = 0.f, h11 = 0.f;
    float z00, z01, z10, z11;

    for (int t = 0; t < 512; t++) {
        float a1[2][4] = {{0,0,0,0},{0,0,0,0}};
        mma_phase<2>(sm, g_hhi, SB1, SB1L, a1, tid, arow, gr, tig);
        {
            const float* x0 = g_xproj + ((size_t)t * 128 + b0r) * 1536 + uc;
            const float* x1 = g_xproj + ((size_t)t * 128 + b1r) * 1536 + uc;
            float2 xz0 = *(const float2*)x0, xr0 = *(const float2*)(x0 + 512);
            float2 xz1 = *(const float2*)x1, xr1 = *(const float2*)(x1 + 512);
            z00 = hsig(xz0.x + a1[0][0]); z01 = hsig(xz0.y + a1[0][1]);
            z10 = hsig(xz1.x + a1[0][2]); z11 = hsig(xz1.y + a1[0][3]);
            float r00 = hsig(xr0.x + a1[1][0]), r01 = hsig(xr0.y + a1[1][1]);
            float r10 = hsig(xr1.x + a1[1][2]), r11 = hsig(xr1.y + a1[1][3]);
            wr_hi(g_rhhi, b0r * 512 + uc, r00 * h00, r01 * h01);
            wr_hi(g_rhhi, b1r * 512 + uc, r10 * h10, r11 * h11);
        }
        gbar(tid, 2 * t + 1);

        float a2[1][4] = {{0,0,0,0}};
        mma_phase<1>(sm, g_rhhi, SB2, SB2L, a2, tid, arow, gr, tig);
        {
            const float* x0 = g_xproj + ((size_t)t * 128 + b0r) * 1536 + 1024 + uc;
            const float* x1 = g_xproj + ((size_t)t * 128 + b1r) * 1536 + 1024 + uc;
            float2 xh0 = *(const float2*)x0, xh1 = *(const float2*)x1;
            float av0 = attn[b0r * 512 + t], av1 = attn[b1r * 512 + t];
            float hh;
            hh = tanhf(xh0.x + a2[0][0]); hh = z00 * h00 + (1.f - z00) * hh; h00 = av0 * hh + (1.f - av0) * h00;
            hh = tanhf(xh0.y + a2[0][1]); hh = z01 * h01 + (1.f - z01) * hh; h01 = av0 * hh + (1.f - av0) * h01;
            hh = tanhf(xh1.x + a2[0][2]); hh = z10 * h10 + (1.f - z10) * hh; h10 = av1 * hh + (1.f - av1) * h10;
            hh = tanhf(xh1.y + a2[0][3]); hh = z11 * h11 + (1.f - z11) * hh; h11 = av1 * hh + (1.f - av1) * h11;
            wr_hi(g_hhi, b0r * 512 + uc, h00, h01);
            wr_hi(g_hhi, b1r * 512 + uc, h10, h11);
            if (t == 511) {
                *(float2*)(out + b0r * 512 + uc) = make_float2(h00, h01);
                *(float2*)(out + b1r * 512 + uc) = make_float2(h10, h11);
            }
        }
        gbar(tid, 2 * t + 2);
    }
}

extern "C" void kernel_launch(void* const* d_in, const int* in_sizes, int n_in,
                              void* d_out, int out_size) {
    cudaFuncSetAttribute(rec_k, cudaFuncAttributeMaxDynamicSharedMemorySize, REC_SMEM);
    cudaFuncSetAttribute(xproj_t_k, cudaFuncAttributeMaxDynamicSharedMemorySize, XP_SMEM);
    noop_k<<<1, 32>>>();
    init_k<<<256, 256>>>((const float*)d_in[1]);
    prep_in_k<<<16384, 256>>>((const float*)d_in[0]);
    prep_w_k<<<dim3(512, 6), 256>>>((const float*)d_in[2]);
    xproj_t_k<<<dim3(512, 12), 256, XP_SMEM>>>((const float*)d_in[4]);
    rec_k<<<NCTA, 256, REC_SMEM>>>((const float*)d_in[3], (const float*)d_in[1], (float*)d_out);
}